// round 1
// baseline (speedup 1.0000x reference)
#include <cuda_runtime.h>
#include <cstdint>

// Problem constants
#define MM   8192          // batch
#define NN   2048          // out features
#define KIN  2048          // in features
#define KK   4096          // fused K = 2*KIN
#define GG   8             // grid last dim
#define NELEM_GRID (KIN*NN*GG)     // 33554432
#define NPART 16384

// GEMM tiling
#define BM 128
#define BN 128
#define BK 16
#define ASTRIDE 20         // BK + 4 pad  -> conflict-free A fragment loads
#define BSTRIDE 136        // BN + 8 pad  -> conflict-free B fragment loads

// -------- device scratch (static globals: allocation-free rule) ----------
__device__ float g_A[(size_t)MM * KK];     // 128 MB  [M][K] tf32-rounded: [x | basis]
__device__ float g_B[(size_t)KK * NN];     //  32 MB  [K][N] tf32-rounded: [Wb^T ; W2]
__device__ float g_part[NPART];
__device__ float g_mean;

// -------- helpers ----------
__device__ __forceinline__ float tf32r(float f) {
    uint32_t u;
    asm("cvt.rna.tf32.f32 %0, %1;" : "=r"(u) : "f"(f));
    return __uint_as_float(u);
}

__device__ __forceinline__ void cp16(void* smem, const void* gmem) {
    uint32_t s = (uint32_t)__cvta_generic_to_shared(smem);
    asm volatile("cp.async.cg.shared.global [%0], [%1], 16;" :: "r"(s), "l"(gmem));
}

// ======================= prep kernel 1: grid reduce =======================
// W2[i][o] = sum_g grid[i][o][g]  -> g_B[(KIN+i)*NN + o]  (tf32-rounded)
// also per-block partial sums for the global mean.
__global__ void k_gridsum(const float* __restrict__ grid) {
    int idx = blockIdx.x * 256 + threadIdx.x;        // idx = i*NN + o
    const float4* g4 = reinterpret_cast<const float4*>(grid);
    float4 p = g4[(size_t)idx * 2];
    float4 q = g4[(size_t)idx * 2 + 1];
    float s = ((p.x + p.y) + (p.z + p.w)) + ((q.x + q.y) + (q.z + q.w));
    int i = idx >> 11;          // / NN
    int o = idx & (NN - 1);
    g_B[(size_t)(KIN + i) * NN + o] = tf32r(s);

    __shared__ float red[256];
    red[threadIdx.x] = s;
    __syncthreads();
    for (int off = 128; off > 0; off >>= 1) {
        if (threadIdx.x < off) red[threadIdx.x] += red[threadIdx.x + off];
        __syncthreads();
    }
    if (threadIdx.x == 0) g_part[blockIdx.x] = red[0];
}

// ======================= prep kernel 2: finalize mean =====================
__global__ void k_mean() {
    __shared__ float red[256];
    float s = 0.f;
    for (int t = threadIdx.x; t < NPART; t += 256) s += g_part[t];
    red[threadIdx.x] = s;
    __syncthreads();
    for (int off = 128; off > 0; off >>= 1) {
        if (threadIdx.x < off) red[threadIdx.x] += red[threadIdx.x + off];
        __syncthreads();
    }
    if (threadIdx.x == 0) g_mean = red[0] * (1.0f / (float)NELEM_GRID);
}

// ======================= prep kernel 3: transpose Wb ======================
// g_B[i*NN + o] = tf32(Wb[o*KIN + i])
__global__ void k_transpose(const float* __restrict__ bw) {
    __shared__ float tile[32][33];
    int bx = blockIdx.x, by = blockIdx.y;
    int tx = threadIdx.x, ty = threadIdx.y;   // 32 x 8
    #pragma unroll
    for (int j = 0; j < 32; j += 8) {
        tile[ty + j][tx] = bw[(size_t)(by * 32 + ty + j) * KIN + bx * 32 + tx];
    }
    __syncthreads();
    #pragma unroll
    for (int j = 0; j < 32; j += 8) {
        g_B[(size_t)(bx * 32 + ty + j) * NN + by * 32 + tx] = tf32r(tile[tx][ty + j]);
    }
}

// ======================= prep kernel 4: build A = [x | basis] =============
__global__ void k_buildA(const float* __restrict__ x) {
    int t = blockIdx.x * 256 + threadIdx.x;          // one float4 of x per thread
    int b  = t >> 9;                                 // row (KIN/4 = 512 float4/row)
    int c4 = t & 511;
    const float4* x4 = reinterpret_cast<const float4*>(x);
    float4 v = x4[(size_t)b * 512 + c4];
    float m = g_mean;
    float4* A4 = reinterpret_cast<float4*>(g_A);
    float4 xv;
    xv.x = tf32r(v.x); xv.y = tf32r(v.y); xv.z = tf32r(v.z); xv.w = tf32r(v.w);
    A4[(size_t)b * 1024 + c4] = xv;
    float dx = v.x - m, dy = v.y - m, dz = v.z - m, dw = v.w - m;
    float4 e;
    e.x = tf32r(__expf(-dx * dx));
    e.y = tf32r(__expf(-dy * dy));
    e.z = tf32r(__expf(-dz * dz));
    e.w = tf32r(__expf(-dw * dw));
    A4[(size_t)b * 1024 + 512 + c4] = e;
}

// ======================= main GEMM: 128x128x16, mma.sync tf32 =============
__device__ __forceinline__ void mma_tf32(float* d, const uint32_t* a, const uint32_t* b) {
    asm volatile(
        "mma.sync.aligned.m16n8k8.row.col.f32.tf32.tf32.f32 "
        "{%0,%1,%2,%3}, {%4,%5,%6,%7}, {%8,%9}, {%0,%1,%2,%3};"
        : "+f"(d[0]), "+f"(d[1]), "+f"(d[2]), "+f"(d[3])
        : "r"(a[0]), "r"(a[1]), "r"(a[2]), "r"(a[3]), "r"(b[0]), "r"(b[1]));
}

__global__ __launch_bounds__(256) void k_gemm(float* __restrict__ out) {
    __shared__ float As[2][BM][ASTRIDE];   // 20480 B
    __shared__ float Bs[2][BK][BSTRIDE];   // 17408 B
    int tid  = threadIdx.x;
    int warp = tid >> 5, lane = tid & 31;
    int wm = warp & 3;        // 4 warps along M
    int wn = warp >> 2;       // 2 warps along N
    int g  = lane >> 2;       // group id 0..7
    int tg = lane & 3;        // thread in group 0..3
    int m0 = blockIdx.y * BM;
    int n0 = blockIdx.x * BN;

    // global->smem load mapping (cp.async 16B)
    int ar = tid >> 2;            // 0..63 : A rows (two passes: ar, ar+64)
    int ac = (tid & 3) * 4;       // A float col 0/4/8/12
    int br = tid >> 5;            // 0..7  : B rows (two passes: br, br+8)
    int bc = (tid & 31) * 4;      // B float col

    const float* Ag = g_A + (size_t)m0 * KK;

    float acc[2][8][4];
    #pragma unroll
    for (int i = 0; i < 2; i++)
        #pragma unroll
        for (int j = 0; j < 8; j++)
            #pragma unroll
            for (int k = 0; k < 4; k++) acc[i][j][k] = 0.f;

    const int NT = KK / BK;   // 256

    // prologue: tile 0 -> buf 0
    {
        cp16(&As[0][ar][ac],      Ag + (size_t)ar        * KK + ac);
        cp16(&As[0][ar + 64][ac], Ag + (size_t)(ar + 64) * KK + ac);
        cp16(&Bs[0][br][bc],      g_B + (size_t)br       * NN + n0 + bc);
        cp16(&Bs[0][br + 8][bc],  g_B + (size_t)(br + 8) * NN + n0 + bc);
        asm volatile("cp.async.commit_group;");
    }

    for (int kt = 0; kt < NT; ++kt) {
        int buf = kt & 1;
        if (kt + 1 < NT) {
            int k0 = (kt + 1) * BK;
            int nb = buf ^ 1;
            cp16(&As[nb][ar][ac],      Ag + (size_t)ar        * KK + k0 + ac);
            cp16(&As[nb][ar + 64][ac], Ag + (size_t)(ar + 64) * KK + k0 + ac);
            cp16(&Bs[nb][br][bc],      g_B + (size_t)(k0 + br)     * NN + n0 + bc);
            cp16(&Bs[nb][br + 8][bc],  g_B + (size_t)(k0 + br + 8) * NN + n0 + bc);
            asm volatile("cp.async.commit_group;");
            asm volatile("cp.async.wait_group 1;");
        } else {
            asm volatile("cp.async.wait_group 0;");
        }
        __syncthreads();

        #pragma unroll
        for (int kk = 0; kk < 2; ++kk) {
            int kb = kk * 8;
            uint32_t a[2][4], bf[8][2];
            #pragma unroll
            for (int am = 0; am < 2; ++am) {
                int mrow = wm * 32 + am * 16;
                a[am][0] = __float_as_uint(As[buf][mrow + g]     [kb + tg]);
                a[am][1] = __float_as_uint(As[buf][mrow + g + 8] [kb + tg]);
                a[am][2] = __float_as_uint(As[buf][mrow + g]     [kb + tg + 4]);
                a[am][3] = __float_as_uint(As[buf][mrow + g + 8] [kb + tg + 4]);
            }
            #pragma unroll
            for (int an = 0; an < 8; ++an) {
                int ncol = wn * 64 + an * 8 + g;
                bf[an][0] = __float_as_uint(Bs[buf][kb + tg]    [ncol]);
                bf[an][1] = __float_as_uint(Bs[buf][kb + tg + 4][ncol]);
            }
            #pragma unroll
            for (int am = 0; am < 2; ++am)
                #pragma unroll
                for (int an = 0; an < 8; ++an)
                    mma_tf32(acc[am][an], a[am], bf[an]);
        }
        __syncthreads();
    }

    // epilogue
    #pragma unroll
    for (int am = 0; am < 2; ++am) {
        #pragma unroll
        for (int an = 0; an < 8; ++an) {
            int row0 = m0 + wm * 32 + am * 16 + g;
            int col  = n0 + wn * 64 + an * 8 + tg * 2;
            float2 v0 = make_float2(acc[am][an][0], acc[am][an][1]);
            float2 v1 = make_float2(acc[am][an][2], acc[am][an][3]);
            *reinterpret_cast<float2*>(&out[(size_t)row0 * NN + col])       = v0;
            *reinterpret_cast<float2*>(&out[(size_t)(row0 + 8) * NN + col]) = v1;
        }
    }
}

// ============================= launch =====================================
extern "C" void kernel_launch(void* const* d_in, const int* in_sizes, int n_in,
                              void* d_out, int out_size) {
    const float* x    = (const float*)d_in[0];   // (8192, 2048)
    const float* bw   = (const float*)d_in[1];   // (2048, 2048)
    const float* grid = (const float*)d_in[2];   // (2048, 2048, 8)
    float* out = (float*)d_out;                  // (8192, 2048)

    k_gridsum<<<NPART, 256>>>(grid);
    k_mean<<<1, 256>>>();
    k_transpose<<<dim3(KIN / 32, NN / 32), dim3(32, 8)>>>(bw);
    k_buildA<<<(MM * KIN / 4) / 256, 256>>>(x);
    k_gemm<<<dim3(NN / BN, MM / BM), 256>>>(out);
}

// round 3
// speedup vs baseline: 1.0465x; 1.0465x over previous
#include <cuda_runtime.h>
#include <cstdint>

// ---------------- problem constants ----------------
#define MM   8192
#define NN   2048
#define KIN  2048
#define KK   4096
#define NPART 4096
#define NELEM_GRID ((size_t)KIN*NN*8)

// ---------------- GEMM tiling ----------------
#define BM 128
#define BN 128
#define BK 16                 // K per stage (floats)
#define ASTR 20               // padded row stride (floats): conflict-free LDSM
#define NSTAGE 4
#define NT (KK / BK)          // 256

#define STAGE_BYTES (128 * ASTR * 4)          // 10240 per operand stage
#define AOFF(s) ((s) * STAGE_BYTES)
#define BOFF(s) (NSTAGE * STAGE_BYTES + (s) * STAGE_BYTES)
#define SMEM_TOTAL (2 * NSTAGE * STAGE_BYTES) // 81920

// ---------------- device scratch ----------------
__device__ float g_A[(size_t)MM * KK];     // [M][K]: [x | basis], tf32-rounded
__device__ float g_B[(size_t)NN * KK];     // [N][K]: [Wb | W2^T], tf32-rounded
__device__ float g_part[NPART];
__device__ float g_mean;

// ---------------- helpers ----------------
__device__ __forceinline__ float tf32r(float f) {
    uint32_t u;
    asm("cvt.rna.tf32.f32 %0, %1;" : "=r"(u) : "f"(f));
    return __uint_as_float(u);
}

__device__ __forceinline__ void cp16(uint32_t smem, const void* gmem) {
    asm volatile("cp.async.cg.shared.global [%0], [%1], 16;" :: "r"(smem), "l"(gmem));
}

__device__ __forceinline__ void ldsm4(uint32_t* r, uint32_t addr) {
    asm volatile("ldmatrix.sync.aligned.m8n8.x4.shared.b16 {%0,%1,%2,%3}, [%4];"
                 : "=r"(r[0]), "=r"(r[1]), "=r"(r[2]), "=r"(r[3]) : "r"(addr));
}

__device__ __forceinline__ void mma_tf32(float* d, const uint32_t* a, const uint32_t* b) {
    asm volatile(
        "mma.sync.aligned.m16n8k8.row.col.f32.tf32.tf32.f32 "
        "{%0,%1,%2,%3}, {%4,%5,%6,%7}, {%8,%9}, {%0,%1,%2,%3};"
        : "+f"(d[0]), "+f"(d[1]), "+f"(d[2]), "+f"(d[3])
        : "r"(a[0]), "r"(a[1]), "r"(a[2]), "r"(a[3]), "r"(b[0]), "r"(b[1]));
}

// ======================= prep 1: grid reduce + transpose ==================
// g_B[o][2048+i] = tf32( sum_g grid[i][o][g] );  partial sums for the mean.
__global__ void k_gridsum(const float* __restrict__ grid) {
    __shared__ float tile[32][33];
    __shared__ float red[256];
    int i0 = blockIdx.x * 32, o0 = blockIdx.y * 32;
    int tx = threadIdx.x & 31, ty = threadIdx.x >> 5;   // 32 x 8
    const float4* g4 = reinterpret_cast<const float4*>(grid);
    float loc = 0.f;
    #pragma unroll
    for (int r = ty; r < 32; r += 8) {
        size_t idx8 = (size_t)(i0 + r) * NN + (o0 + tx);
        float4 p = g4[idx8 * 2];
        float4 q = g4[idx8 * 2 + 1];
        float s = ((p.x + p.y) + (p.z + p.w)) + ((q.x + q.y) + (q.z + q.w));
        tile[r][tx] = s;
        loc += s;
    }
    red[threadIdx.x] = loc;
    __syncthreads();
    #pragma unroll
    for (int r = ty; r < 32; r += 8)
        g_B[(size_t)(o0 + r) * KK + KIN + i0 + tx] = tf32r(tile[tx][r]);
    for (int off = 128; off > 0; off >>= 1) {
        if (threadIdx.x < off) red[threadIdx.x] += red[threadIdx.x + off];
        __syncthreads();
    }
    if (threadIdx.x == 0) g_part[blockIdx.y * 64 + blockIdx.x] = red[0];
}

// ======================= prep 2: finalize mean ============================
__global__ void k_mean() {
    __shared__ float red[256];
    float s = 0.f;
    for (int t = threadIdx.x; t < NPART; t += 256) s += g_part[t];
    red[threadIdx.x] = s;
    __syncthreads();
    for (int off = 128; off > 0; off >>= 1) {
        if (threadIdx.x < off) red[threadIdx.x] += red[threadIdx.x + off];
        __syncthreads();
    }
    if (threadIdx.x == 0) g_mean = red[0] * (1.0f / (float)NELEM_GRID);
}

// ======================= prep 3: round Wb into B[N][0:2048] ===============
__global__ void k_roundWb(const float* __restrict__ bw) {
    int t = blockIdx.x * 256 + threadIdx.x;      // one float4
    int n = t >> 9, k4 = t & 511;
    const float4* s4 = reinterpret_cast<const float4*>(bw);
    float4 v = s4[(size_t)t];
    float4 r;
    r.x = tf32r(v.x); r.y = tf32r(v.y); r.z = tf32r(v.z); r.w = tf32r(v.w);
    reinterpret_cast<float4*>(g_B)[(size_t)n * (KK / 4) + k4] = r;
}

// ======================= prep 4: build A = [x | basis] ====================
__global__ void k_buildA(const float* __restrict__ x) {
    int t = blockIdx.x * 256 + threadIdx.x;
    int b = t >> 9, c4 = t & 511;
    const float4* x4 = reinterpret_cast<const float4*>(x);
    float4 v = x4[(size_t)b * 512 + c4];
    float m = g_mean;
    float4* A4 = reinterpret_cast<float4*>(g_A);
    float4 xv;
    xv.x = tf32r(v.x); xv.y = tf32r(v.y); xv.z = tf32r(v.z); xv.w = tf32r(v.w);
    A4[(size_t)b * (KK / 4) + c4] = xv;
    float dx = v.x - m, dy = v.y - m, dz = v.z - m, dw = v.w - m;
    float4 e;
    e.x = tf32r(__expf(-dx * dx));
    e.y = tf32r(__expf(-dy * dy));
    e.z = tf32r(__expf(-dz * dz));
    e.w = tf32r(__expf(-dw * dw));
    A4[(size_t)b * (KK / 4) + (KIN / 4) + c4] = e;
}

// ======================= main GEMM: 128x128x16, ldmatrix + mma.sync =======
__global__ __launch_bounds__(256) void k_gemm(float* __restrict__ out) {
    extern __shared__ char smc[];
    uint32_t sb = (uint32_t)__cvta_generic_to_shared(smc);

    int tid  = threadIdx.x;
    int warp = tid >> 5, lane = tid & 31;
    int wm = warp & 3;         // 4 warps along M -> 32 rows each
    int wn = warp >> 2;        // 2 warps along N -> 64 cols each
    int g  = lane >> 2;        // 0..7
    int tg = lane & 3;         // 0..3
    int m0 = blockIdx.y * BM;
    int n0 = blockIdx.x * BN;

    // ldmatrix lane address offsets (bytes within a stage)
    int li = lane >> 3;        // matrix id 0..3
    int lr = lane & 7;         // row within matrix
    // A: matrices (m-half = li&1, k-half = li>>1)
    uint32_t a_base = ((wm * 32 + (li & 1) * 8 + lr) * ASTR + (li >> 1) * 4) * 4;
    // B: matrices (k-half = li&1, n-tile = li>>1)
    uint32_t b_base = ((wn * 64 + (li >> 1) * 8 + lr) * ASTR + (li & 1) * 4) * 4;

    // cp.async mapping: 512 16B-chunks per operand, 2 per thread
    int r0 = tid >> 2;               // rows 0..63 (second pass +64)
    int kc = (tid & 3);              // k-chunk 0..3 (16B each)
    const float* Ag0 = g_A + (size_t)(m0 + r0)      * KK + kc * 4;
    const float* Ag1 = g_A + (size_t)(m0 + r0 + 64) * KK + kc * 4;
    const float* Bg0 = g_B + (size_t)(n0 + r0)      * KK + kc * 4;
    const float* Bg1 = g_B + (size_t)(n0 + r0 + 64) * KK + kc * 4;
    uint32_t da0 = r0 * (ASTR * 4) + kc * 16;
    uint32_t da1 = (r0 + 64) * (ASTR * 4) + kc * 16;

    float acc[2][8][4];
    #pragma unroll
    for (int i = 0; i < 2; i++)
        #pragma unroll
        for (int j = 0; j < 8; j++)
            #pragma unroll
            for (int k = 0; k < 4; k++) acc[i][j][k] = 0.f;

    // prologue: stages 0..2
    #pragma unroll
    for (int s = 0; s < NSTAGE - 1; ++s) {
        int k0 = s * BK;
        cp16(sb + AOFF(s) + da0, Ag0 + k0);
        cp16(sb + AOFF(s) + da1, Ag1 + k0);
        cp16(sb + BOFF(s) + da0, Bg0 + k0);
        cp16(sb + BOFF(s) + da1, Bg1 + k0);
        asm volatile("cp.async.commit_group;");
    }

    #pragma unroll 1
    for (int kt = 0; kt < NT; ++kt) {
        asm volatile("cp.async.wait_group %0;" :: "n"(NSTAGE - 2));
        __syncthreads();

        // prefetch stage kt+3 into buffer freed by compute of kt-1
        if (kt + NSTAGE - 1 < NT) {
            int s  = (kt + NSTAGE - 1) & (NSTAGE - 1);
            int k0 = (kt + NSTAGE - 1) * BK;
            cp16(sb + AOFF(s) + da0, Ag0 + k0);
            cp16(sb + AOFF(s) + da1, Ag1 + k0);
            cp16(sb + BOFF(s) + da0, Bg0 + k0);
            cp16(sb + BOFF(s) + da1, Bg1 + k0);
        }
        asm volatile("cp.async.commit_group;");

        int buf = kt & (NSTAGE - 1);
        uint32_t abase = sb + AOFF(buf) + a_base;
        uint32_t bbase = sb + BOFF(buf) + b_base;

        #pragma unroll
        for (int kb = 0; kb < 2; ++kb) {         // two k8 slices
            uint32_t af[2][4], bf[2][4];         // bf[bt pair][4]: {b0 t0, b1 t0, b0 t1, b1 t1}
            ldsm4(af[0], abase + kb * 32);
            ldsm4(af[1], abase + kb * 32 + 16 * ASTR * 4);
            #pragma unroll
            for (int bp = 0; bp < 4; ++bp) {     // 4 pairs of n8-tiles
                uint32_t bt[4];
                ldsm4(bt, bbase + kb * 32 + bp * (16 * ASTR * 4));
                uint32_t bA[2] = {bt[0], bt[1]};
                uint32_t bB[2] = {bt[2], bt[3]};
                #pragma unroll
                for (int am = 0; am < 2; ++am) {
                    mma_tf32(acc[am][bp * 2 + 0], af[am], bA);
                    mma_tf32(acc[am][bp * 2 + 1], af[am], bB);
                }
            }
        }
        __syncthreads();
    }

    // epilogue
    #pragma unroll
    for (int am = 0; am < 2; ++am) {
        #pragma unroll
        for (int an = 0; an < 8; ++an) {
            int row0 = m0 + wm * 32 + am * 16 + g;
            int col  = n0 + wn * 64 + an * 8 + tg * 2;
            float2 v0 = make_float2(acc[am][an][0], acc[am][an][1]);
            float2 v1 = make_float2(acc[am][an][2], acc[am][an][3]);
            *reinterpret_cast<float2*>(&out[(size_t)row0 * NN + col])       = v0;
            *reinterpret_cast<float2*>(&out[(size_t)(row0 + 8) * NN + col]) = v1;
        }
    }
}

// ============================= launch =====================================
extern "C" void kernel_launch(void* const* d_in, const int* in_sizes, int n_in,
                              void* d_out, int out_size) {
    const float* x    = (const float*)d_in[0];   // (8192, 2048)
    const float* bw   = (const float*)d_in[1];   // (2048, 2048)
    const float* grid = (const float*)d_in[2];   // (2048, 2048, 8)
    float* out = (float*)d_out;                  // (8192, 2048)

    cudaFuncSetAttribute(k_gemm, cudaFuncAttributeMaxDynamicSharedMemorySize, SMEM_TOTAL);

    k_gridsum<<<dim3(KIN / 32, NN / 32), 256>>>(grid);
    k_roundWb<<<(NN * KIN / 4) / 256, 256>>>(bw);
    k_mean<<<1, 256>>>();
    k_buildA<<<(MM * KIN / 4) / 256, 256>>>(x);
    k_gemm<<<dim3(NN / BN, MM / BM), 256, SMEM_TOTAL>>>(out);
}